// round 4
// baseline (speedup 1.0000x reference)
#include <cuda_runtime.h>
#include <cuda_fp16.h>

#define N_X   20000
#define N_ELL 48
#define N_K   1024
#define N_TAU 600

#define N_CHUNK 15
#define T_PER_CHUNK (N_TAU / N_CHUNK)   // 40
#define K_PER_BLOCK 32                   // 2 per thread
#define KCOLS 16
#define NG 12                            // ell groups of 4

// Scratch partial sums: [chunk][ell][k]
__device__ float g_Tl[N_CHUNK][N_ELL][N_K];
__device__ float g_El[N_CHUNK][N_ELL][N_K];

// Packed fp16 tables: row i0, group g -> 16 halves (p0 x4, p1 x4, p2 x4, pe x4)
// row stride = 24 uint4 (384 B)
__device__ uint4 g_pack[N_X * 24];

__device__ __forceinline__ unsigned h2u(__half2 h) {
    return *reinterpret_cast<unsigned*>(&h);
}
__device__ __forceinline__ __half2 u2h(unsigned u) {
    __half2 h; *reinterpret_cast<unsigned*>(&h) = u; return h;
}

// ---------------------------------------------------------------------------
// Kernel 0: pack 4 float tables -> interleaved fp16. 2 entries per thread.
// ---------------------------------------------------------------------------
#define HALF_ENT (N_X * NG / 2)          // 120000
__global__ __launch_bounds__(256) void pack_tables(
    const float* __restrict__ p0t, const float* __restrict__ p1t,
    const float* __restrict__ p2t, const float* __restrict__ pet)
{
    const int tid = blockIdx.x * 256 + threadIdx.x;
    if (tid >= HALF_ENT) return;
    const float4* __restrict__ P0 = (const float4*)p0t;
    const float4* __restrict__ P1 = (const float4*)p1t;
    const float4* __restrict__ P2 = (const float4*)p2t;
    const float4* __restrict__ PE = (const float4*)pet;

    #pragma unroll
    for (int h = 0; h < 2; ++h) {
        const int e = tid + h * HALF_ENT;
        const float4 v0 = P0[e], v1 = P1[e], v2 = P2[e], ve = PE[e];
        uint4 oA, oB;
        oA.x = h2u(__float22half2_rn(make_float2(v0.x, v0.y)));
        oA.y = h2u(__float22half2_rn(make_float2(v0.z, v0.w)));
        oA.z = h2u(__float22half2_rn(make_float2(v1.x, v1.y)));
        oA.w = h2u(__float22half2_rn(make_float2(v1.z, v1.w)));
        oB.x = h2u(__float22half2_rn(make_float2(v2.x, v2.y)));
        oB.y = h2u(__float22half2_rn(make_float2(v2.z, v2.w)));
        oB.z = h2u(__float22half2_rn(make_float2(ve.x, ve.y)));
        oB.w = h2u(__float22half2_rn(make_float2(ve.z, ve.w)));
        g_pack[e * 2]     = oA;
        g_pack[e * 2 + 1] = oB;
    }
}

// ---------------------------------------------------------------------------
// Kernel 1: fused interpolation + source product + tau-trapezoid partials.
// block (12,16) = 192 threads; each thread: 2 k-values x 4 ells.
// grid: (32 k-blocks, 15 tau-chunks) = 480 blocks.
// ---------------------------------------------------------------------------
__global__ __launch_bounds__(192) void spectrum_k1(
    const float* __restrict__ kk_arr,
    const float* __restrict__ tau,
    const float* __restrict__ tau0p,
    const float* __restrict__ S0,
    const float* __restrict__ S1,
    const float* __restrict__ S2,
    const float* __restrict__ SE,
    const float* __restrict__ bx)
{
    __shared__ float sh_d[T_PER_CHUNK];
    __shared__ float sh_w[T_PER_CHUNK];

    const int chunk = blockIdx.y;
    const int t0    = chunk * T_PER_CHUNK;
    const int tid   = threadIdx.y * NG + threadIdx.x;

    const float tau0 = tau0p[0];
    for (int t = tid; t < T_PER_CHUNK; t += 192) {
        const int tg = t0 + t;
        sh_d[t] = tau0 - tau[tg];
        const float wl = (tg == 0)         ? 0.0f : (tau[tg] - tau[tg - 1]);
        const float wr = (tg == N_TAU - 1) ? 0.0f : (tau[tg + 1] - tau[tg]);
        sh_w[t] = 0.5f * (wl + wr);
    }
    __syncthreads();

    const int kA = blockIdx.x * K_PER_BLOCK + threadIdx.y;        // first k
    const int kB = kA + KCOLS;                                    // second k
    const float kvA = kk_arr[kA];
    const float kvB = kk_arr[kB];
    const int g2 = threadIdx.x * 2;

    const float xmin = bx[0];
    const float xmax = bx[N_X - 1];
    const float sc   = (float)(N_X - 1) / (xmax - xmin);

    float aT0 = 0.f, aT1 = 0.f, aT2 = 0.f, aT3 = 0.f;
    float aE0 = 0.f, aE1 = 0.f, aE2 = 0.f, aE3 = 0.f;
    float bT0 = 0.f, bT1 = 0.f, bT2 = 0.f, bT3 = 0.f;
    float bE0 = 0.f, bE1 = 0.f, bE2 = 0.f, bE3 = 0.f;

    const int sbA = kA * N_TAU + t0;
    const int sbB = kB * N_TAU + t0;
    const uint4* __restrict__ TP = g_pack;

    #pragma unroll 2
    for (int t = 0; t < T_PER_CHUNK; ++t) {
        const float d  = sh_d[t];
        const float wt = sh_w[t];

        // --- addresses for both k ---
        float posA = (kvA * d - xmin) * sc;
        posA = fminf(fmaxf(posA, 0.0f), (float)(N_X - 1));
        int iA = (int)posA; if (iA > N_X - 2) iA = N_X - 2;
        const float wA = posA - (float)iA;
        const int raA = iA * 24 + g2;

        float posB = (kvB * d - xmin) * sc;
        posB = fminf(fmaxf(posB, 0.0f), (float)(N_X - 1));
        int iB = (int)posB; if (iB > N_X - 2) iB = N_X - 2;
        const float wB = posB - (float)iB;
        const int raB = iB * 24 + g2;

        // --- 8 independent table loads (front-batched) ---
        const uint4 A0 = TP[raA],      A1 = TP[raA + 1];
        const uint4 A2 = TP[raA + 24], A3 = TP[raA + 25];
        const uint4 C0 = TP[raB],      C1 = TP[raB + 1];
        const uint4 C2 = TP[raB + 24], C3 = TP[raB + 25];

        // --- sources ---
        const float sA0 = S0[sbA + t] * wt;
        const float sA1 = S1[sbA + t] * wt;
        const float sA2 = S2[sbA + t] * wt;
        const float sAe = SE[sbA + t] * wt;
        const float sB0 = S0[sbB + t] * wt;
        const float sB1 = S1[sbB + t] * wt;
        const float sB2 = S2[sbB + t] * wt;
        const float sBe = SE[sbB + t] * wt;

        // --- lerp + accumulate, k = A ---
        {
            const __half2 w2 = __float2half2_rn(wA);
            const __half2 h0a = __hfma2(w2, __hsub2(u2h(A2.x), u2h(A0.x)), u2h(A0.x));
            const __half2 h0b = __hfma2(w2, __hsub2(u2h(A2.y), u2h(A0.y)), u2h(A0.y));
            const __half2 h1a = __hfma2(w2, __hsub2(u2h(A2.z), u2h(A0.z)), u2h(A0.z));
            const __half2 h1b = __hfma2(w2, __hsub2(u2h(A2.w), u2h(A0.w)), u2h(A0.w));
            const __half2 h2a = __hfma2(w2, __hsub2(u2h(A3.x), u2h(A1.x)), u2h(A1.x));
            const __half2 h2b = __hfma2(w2, __hsub2(u2h(A3.y), u2h(A1.y)), u2h(A1.y));
            const __half2 hea = __hfma2(w2, __hsub2(u2h(A3.z), u2h(A1.z)), u2h(A1.z));
            const __half2 heb = __hfma2(w2, __hsub2(u2h(A3.w), u2h(A1.w)), u2h(A1.w));
            const float2 f0a = __half22float2(h0a), f0b = __half22float2(h0b);
            const float2 f1a = __half22float2(h1a), f1b = __half22float2(h1b);
            const float2 f2a = __half22float2(h2a), f2b = __half22float2(h2b);
            const float2 fea = __half22float2(hea), feb = __half22float2(heb);
            aT0 += sA0 * f0a.x + sA1 * f1a.x + sA2 * f2a.x;
            aT1 += sA0 * f0a.y + sA1 * f1a.y + sA2 * f2a.y;
            aT2 += sA0 * f0b.x + sA1 * f1b.x + sA2 * f2b.x;
            aT3 += sA0 * f0b.y + sA1 * f1b.y + sA2 * f2b.y;
            aE0 += sAe * fea.x;
            aE1 += sAe * fea.y;
            aE2 += sAe * feb.x;
            aE3 += sAe * feb.y;
        }
        // --- lerp + accumulate, k = B ---
        {
            const __half2 w2 = __float2half2_rn(wB);
            const __half2 h0a = __hfma2(w2, __hsub2(u2h(C2.x), u2h(C0.x)), u2h(C0.x));
            const __half2 h0b = __hfma2(w2, __hsub2(u2h(C2.y), u2h(C0.y)), u2h(C0.y));
            const __half2 h1a = __hfma2(w2, __hsub2(u2h(C2.z), u2h(C0.z)), u2h(C0.z));
            const __half2 h1b = __hfma2(w2, __hsub2(u2h(C2.w), u2h(C0.w)), u2h(C0.w));
            const __half2 h2a = __hfma2(w2, __hsub2(u2h(C3.x), u2h(C1.x)), u2h(C1.x));
            const __half2 h2b = __hfma2(w2, __hsub2(u2h(C3.y), u2h(C1.y)), u2h(C1.y));
            const __half2 hea = __hfma2(w2, __hsub2(u2h(C3.z), u2h(C1.z)), u2h(C1.z));
            const __half2 heb = __hfma2(w2, __hsub2(u2h(C3.w), u2h(C1.w)), u2h(C1.w));
            const float2 f0a = __half22float2(h0a), f0b = __half22float2(h0b);
            const float2 f1a = __half22float2(h1a), f1b = __half22float2(h1b);
            const float2 f2a = __half22float2(h2a), f2b = __half22float2(h2b);
            const float2 fea = __half22float2(hea), feb = __half22float2(heb);
            bT0 += sB0 * f0a.x + sB1 * f1a.x + sB2 * f2a.x;
            bT1 += sB0 * f0a.y + sB1 * f1a.y + sB2 * f2a.y;
            bT2 += sB0 * f0b.x + sB1 * f1b.x + sB2 * f2b.x;
            bT3 += sB0 * f0b.y + sB1 * f1b.y + sB2 * f2b.y;
            bE0 += sBe * fea.x;
            bE1 += sBe * fea.y;
            bE2 += sBe * feb.x;
            bE3 += sBe * feb.y;
        }
    }

    const int ell = 4 * threadIdx.x;
    g_Tl[chunk][ell + 0][kA] = aT0;
    g_Tl[chunk][ell + 1][kA] = aT1;
    g_Tl[chunk][ell + 2][kA] = aT2;
    g_Tl[chunk][ell + 3][kA] = aT3;
    g_El[chunk][ell + 0][kA] = aE0;
    g_El[chunk][ell + 1][kA] = aE1;
    g_El[chunk][ell + 2][kA] = aE2;
    g_El[chunk][ell + 3][kA] = aE3;
    g_Tl[chunk][ell + 0][kB] = bT0;
    g_Tl[chunk][ell + 1][kB] = bT1;
    g_Tl[chunk][ell + 2][kB] = bT2;
    g_Tl[chunk][ell + 3][kB] = bT3;
    g_El[chunk][ell + 0][kB] = bE0;
    g_El[chunk][ell + 1][kB] = bE1;
    g_El[chunk][ell + 2][kB] = bE2;
    g_El[chunk][ell + 3][kB] = bE3;
}

// ---------------------------------------------------------------------------
// Kernel 2: k-quadrature -> Cl.  48 blocks, 512 threads.
// ---------------------------------------------------------------------------
__global__ __launch_bounds__(512) void spectrum_k2(
    const float* __restrict__ kk_arr,
    const float* __restrict__ Asp,
    const float* __restrict__ nsp,
    float* __restrict__ out)
{
    const int ell = blockIdx.x;
    const int tid = threadIdx.x;

    const float A_s  = Asp[0];
    const float n_s  = nsp[0];
    const float PI_F = 3.14159265358979323846f;
    const float pref = A_s * 2.0f * PI_F * PI_F;

    double tt = 0.0, ee = 0.0, te = 0.0;
    for (int i = tid; i < N_K; i += 512) {
        const float kv = kk_arr[i];
        const float wl = (i == 0)        ? 0.0f : (kv - kk_arr[i - 1]);
        const float wr = (i == N_K - 1)  ? 0.0f : (kk_arr[i + 1] - kv);
        const float pw = exp2f((n_s - 1.0f) * log2f(kv * 20.0f));
        const float weight = 0.5f * (wl + wr) * pref * pw / kv;

        float T = 0.f, E = 0.f;
        #pragma unroll
        for (int c = 0; c < N_CHUNK; ++c) {
            T += g_Tl[c][ell][i];
            E += g_El[c][ell][i];
        }
        tt += (double)(weight * T * T);
        ee += (double)(weight * E * E);
        te += (double)(weight * T * E);
    }

    #pragma unroll
    for (int o = 16; o > 0; o >>= 1) {
        tt += __shfl_down_sync(0xffffffffu, tt, o);
        ee += __shfl_down_sync(0xffffffffu, ee, o);
        te += __shfl_down_sync(0xffffffffu, te, o);
    }
    __shared__ double sT[16], sE[16], sX[16];
    const int wid = tid >> 5, lid = tid & 31;
    if (lid == 0) { sT[wid] = tt; sE[wid] = ee; sX[wid] = te; }
    __syncthreads();
    if (tid < 16) {
        tt = sT[tid]; ee = sE[tid]; te = sX[tid];
        #pragma unroll
        for (int o = 8; o > 0; o >>= 1) {
            tt += __shfl_down_sync(0xffffu, tt, o, 16);
            ee += __shfl_down_sync(0xffffu, ee, o, 16);
            te += __shfl_down_sync(0xffffu, te, o, 16);
        }
        if (tid == 0) {
            const double c = 2.0 / 3.14159265358979323846;
            out[0 * N_ELL + ell] = (float)(c * tt);
            out[1 * N_ELL + ell] = (float)(c * ee);
            out[2 * N_ELL + ell] = (float)(c * te);
        }
    }
}

extern "C" void kernel_launch(void* const* d_in, const int* in_sizes, int n_in,
                              void* d_out, int out_size)
{
    const float* k    = (const float*)d_in[0];
    const float* tau  = (const float*)d_in[1];
    const float* tau0 = (const float*)d_in[2];
    const float* S0   = (const float*)d_in[3];
    const float* S1   = (const float*)d_in[4];
    const float* S2   = (const float*)d_in[5];
    const float* SE   = (const float*)d_in[6];
    const float* bx   = (const float*)d_in[7];
    const float* p0   = (const float*)d_in[8];
    const float* p1   = (const float*)d_in[9];
    const float* p2   = (const float*)d_in[10];
    const float* pe   = (const float*)d_in[11];
    const float* As   = (const float*)d_in[12];
    const float* ns   = (const float*)d_in[13];
    float* out = (float*)d_out;

    pack_tables<<<(HALF_ENT + 255) / 256, 256>>>(p0, p1, p2, pe);

    dim3 grid1(N_K / K_PER_BLOCK, N_CHUNK);   // (32, 15)
    dim3 block1(NG, KCOLS);                   // (12, 16) = 192 threads
    spectrum_k1<<<grid1, block1>>>(k, tau, tau0, S0, S1, S2, SE, bx);

    spectrum_k2<<<N_ELL, 512>>>(k, As, ns, out);
}

// round 5
// speedup vs baseline: 1.0905x; 1.0905x over previous
#include <cuda_runtime.h>
#include <cuda_fp16.h>

#define N_X   20000
#define N_ELL 48
#define N_K   1024
#define N_TAU 600

#define N_CHUNK 12
#define T_PER_CHUNK (N_TAU / N_CHUNK)   // 50
#define K_PER_BLOCK 16
#define NG 12                            // ell groups of 4

// Scratch partial sums: [chunk][ell][k]
__device__ float g_Tl[N_CHUNK][N_ELL][N_K];
__device__ float g_El[N_CHUNK][N_ELL][N_K];

// Packed fp16 tables: row i0, group g -> 16 halves (p0 x4, p1 x4, p2 x4, pe x4)
// row stride = 24 uint4 (384 B)
__device__ uint4 g_pack[N_X * 24];

// Precomputed per-(k,t): wt-premultiplied sources and (i0*24, w)
__device__ float4 g_Spack[N_K * N_TAU];
__device__ float2 g_iw[N_K * N_TAU];

__device__ __forceinline__ unsigned h2u(__half2 h) {
    return *reinterpret_cast<unsigned*>(&h);
}
__device__ __forceinline__ __half2 u2h(unsigned u) {
    __half2 h; *reinterpret_cast<unsigned*>(&h) = u; return h;
}

#define TAB_ENT   (N_X * NG)                       // 240000
#define TAB_BLK   ((TAB_ENT + 255) / 256)          // 938
#define SRC_ENT   (N_K * N_TAU)                    // 614400
#define SRC_BLK   ((SRC_ENT + 255) / 256)          // 2400

// ---------------------------------------------------------------------------
// Kernel 0: (a) pack 4 float tables -> interleaved fp16,
//           (b) build Spack (wt-premultiplied sources) and iw (i0, w).
// ---------------------------------------------------------------------------
__global__ __launch_bounds__(256) void prep_kernel(
    const float* __restrict__ p0t, const float* __restrict__ p1t,
    const float* __restrict__ p2t, const float* __restrict__ pet,
    const float* __restrict__ kk_arr,
    const float* __restrict__ tau,
    const float* __restrict__ tau0p,
    const float* __restrict__ S0,
    const float* __restrict__ S1,
    const float* __restrict__ S2,
    const float* __restrict__ SE,
    const float* __restrict__ bx)
{
    if (blockIdx.x < TAB_BLK) {
        const int tid = blockIdx.x * 256 + threadIdx.x;
        if (tid >= TAB_ENT) return;
        const float4* __restrict__ P0 = (const float4*)p0t;
        const float4* __restrict__ P1 = (const float4*)p1t;
        const float4* __restrict__ P2 = (const float4*)p2t;
        const float4* __restrict__ PE = (const float4*)pet;
        const float4 v0 = P0[tid], v1 = P1[tid], v2 = P2[tid], ve = PE[tid];
        uint4 oA, oB;
        oA.x = h2u(__float22half2_rn(make_float2(v0.x, v0.y)));
        oA.y = h2u(__float22half2_rn(make_float2(v0.z, v0.w)));
        oA.z = h2u(__float22half2_rn(make_float2(v1.x, v1.y)));
        oA.w = h2u(__float22half2_rn(make_float2(v1.z, v1.w)));
        oB.x = h2u(__float22half2_rn(make_float2(v2.x, v2.y)));
        oB.y = h2u(__float22half2_rn(make_float2(v2.z, v2.w)));
        oB.z = h2u(__float22half2_rn(make_float2(ve.x, ve.y)));
        oB.w = h2u(__float22half2_rn(make_float2(ve.z, ve.w)));
        g_pack[tid * 2]     = oA;
        g_pack[tid * 2 + 1] = oB;
    } else {
        const int e = (blockIdx.x - TAB_BLK) * 256 + threadIdx.x;
        if (e >= SRC_ENT) return;
        const int kidx = e / N_TAU;
        const int t    = e - kidx * N_TAU;

        const float tau0 = tau0p[0];
        const float tv   = tau[t];
        const float wl = (t == 0)         ? 0.0f : (tv - tau[t - 1]);
        const float wr = (t == N_TAU - 1) ? 0.0f : (tau[t + 1] - tv);
        const float wt = 0.5f * (wl + wr);

        const float xmin = bx[0];
        const float xmax = bx[N_X - 1];
        const float sc   = (float)(N_X - 1) / (xmax - xmin);

        const float x = kk_arr[kidx] * (tau0 - tv);
        float pos = (x - xmin) * sc;
        pos = fminf(fmaxf(pos, 0.0f), (float)(N_X - 1));
        int i0 = (int)pos;
        if (i0 > N_X - 2) i0 = N_X - 2;

        g_iw[e]    = make_float2(__int_as_float(i0 * 24), pos - (float)i0);
        g_Spack[e] = make_float4(S0[e] * wt, S1[e] * wt, S2[e] * wt, SE[e] * wt);
    }
}

// ---------------------------------------------------------------------------
// Kernel 1: pure gather + lerp + accumulate.  block (12,16), grid (64,12).
// Each iteration handles 2 tau-steps sharing accumulators.
// ---------------------------------------------------------------------------
__global__ __launch_bounds__(192) void spectrum_k1()
{
    const int chunk = blockIdx.y;
    const int t0    = chunk * T_PER_CHUNK;
    const int kidx  = blockIdx.x * K_PER_BLOCK + threadIdx.y;
    const int g2    = threadIdx.x * 2;

    float aT0 = 0.f, aT1 = 0.f, aT2 = 0.f, aT3 = 0.f;
    float aE0 = 0.f, aE1 = 0.f, aE2 = 0.f, aE3 = 0.f;

    const int base = kidx * N_TAU + t0;
    const uint4*  __restrict__ TP = g_pack;
    const float4* __restrict__ SP = g_Spack;
    const float2* __restrict__ IW = g_iw;

    #pragma unroll 2
    for (int t = 0; t < T_PER_CHUNK; t += 2) {
        // front-batched scalar/meta loads (warp-broadcast across 12 g-lanes)
        const float2 iwA = IW[base + t];
        const float2 iwB = IW[base + t + 1];
        const float4 sA  = SP[base + t];
        const float4 sB  = SP[base + t + 1];

        const int raA = __float_as_int(iwA.x) + g2;
        const int raB = __float_as_int(iwB.x) + g2;

        // 8 independent table loads
        const uint4 A0 = TP[raA],      A1 = TP[raA + 1];
        const uint4 A2 = TP[raA + 24], A3 = TP[raA + 25];
        const uint4 C0 = TP[raB],      C1 = TP[raB + 1];
        const uint4 C2 = TP[raB + 24], C3 = TP[raB + 25];

        {
            const __half2 w2 = __float2half2_rn(iwA.y);
            const __half2 h0a = __hfma2(w2, __hsub2(u2h(A2.x), u2h(A0.x)), u2h(A0.x));
            const __half2 h0b = __hfma2(w2, __hsub2(u2h(A2.y), u2h(A0.y)), u2h(A0.y));
            const __half2 h1a = __hfma2(w2, __hsub2(u2h(A2.z), u2h(A0.z)), u2h(A0.z));
            const __half2 h1b = __hfma2(w2, __hsub2(u2h(A2.w), u2h(A0.w)), u2h(A0.w));
            const __half2 h2a = __hfma2(w2, __hsub2(u2h(A3.x), u2h(A1.x)), u2h(A1.x));
            const __half2 h2b = __hfma2(w2, __hsub2(u2h(A3.y), u2h(A1.y)), u2h(A1.y));
            const __half2 hea = __hfma2(w2, __hsub2(u2h(A3.z), u2h(A1.z)), u2h(A1.z));
            const __half2 heb = __hfma2(w2, __hsub2(u2h(A3.w), u2h(A1.w)), u2h(A1.w));
            const float2 f0a = __half22float2(h0a), f0b = __half22float2(h0b);
            const float2 f1a = __half22float2(h1a), f1b = __half22float2(h1b);
            const float2 f2a = __half22float2(h2a), f2b = __half22float2(h2b);
            const float2 fea = __half22float2(hea), feb = __half22float2(heb);
            aT0 += sA.x * f0a.x + sA.y * f1a.x + sA.z * f2a.x;
            aT1 += sA.x * f0a.y + sA.y * f1a.y + sA.z * f2a.y;
            aT2 += sA.x * f0b.x + sA.y * f1b.x + sA.z * f2b.x;
            aT3 += sA.x * f0b.y + sA.y * f1b.y + sA.z * f2b.y;
            aE0 += sA.w * fea.x;
            aE1 += sA.w * fea.y;
            aE2 += sA.w * feb.x;
            aE3 += sA.w * feb.y;
        }
        {
            const __half2 w2 = __float2half2_rn(iwB.y);
            const __half2 h0a = __hfma2(w2, __hsub2(u2h(C2.x), u2h(C0.x)), u2h(C0.x));
            const __half2 h0b = __hfma2(w2, __hsub2(u2h(C2.y), u2h(C0.y)), u2h(C0.y));
            const __half2 h1a = __hfma2(w2, __hsub2(u2h(C2.z), u2h(C0.z)), u2h(C0.z));
            const __half2 h1b = __hfma2(w2, __hsub2(u2h(C2.w), u2h(C0.w)), u2h(C0.w));
            const __half2 h2a = __hfma2(w2, __hsub2(u2h(C3.x), u2h(C1.x)), u2h(C1.x));
            const __half2 h2b = __hfma2(w2, __hsub2(u2h(C3.y), u2h(C1.y)), u2h(C1.y));
            const __half2 hea = __hfma2(w2, __hsub2(u2h(C3.z), u2h(C1.z)), u2h(C1.z));
            const __half2 heb = __hfma2(w2, __hsub2(u2h(C3.w), u2h(C1.w)), u2h(C1.w));
            const float2 f0a = __half22float2(h0a), f0b = __half22float2(h0b);
            const float2 f1a = __half22float2(h1a), f1b = __half22float2(h1b);
            const float2 f2a = __half22float2(h2a), f2b = __half22float2(h2b);
            const float2 fea = __half22float2(hea), feb = __half22float2(heb);
            aT0 += sB.x * f0a.x + sB.y * f1a.x + sB.z * f2a.x;
            aT1 += sB.x * f0a.y + sB.y * f1a.y + sB.z * f2a.y;
            aT2 += sB.x * f0b.x + sB.y * f1b.x + sB.z * f2b.x;
            aT3 += sB.x * f0b.y + sB.y * f1b.y + sB.z * f2b.y;
            aE0 += sB.w * fea.x;
            aE1 += sB.w * fea.y;
            aE2 += sB.w * feb.x;
            aE3 += sB.w * feb.y;
        }
    }

    const int ell = 4 * threadIdx.x;
    g_Tl[chunk][ell + 0][kidx] = aT0;
    g_Tl[chunk][ell + 1][kidx] = aT1;
    g_Tl[chunk][ell + 2][kidx] = aT2;
    g_Tl[chunk][ell + 3][kidx] = aT3;
    g_El[chunk][ell + 0][kidx] = aE0;
    g_El[chunk][ell + 1][kidx] = aE1;
    g_El[chunk][ell + 2][kidx] = aE2;
    g_El[chunk][ell + 3][kidx] = aE3;
}

// ---------------------------------------------------------------------------
// Kernel 2: k-quadrature -> Cl.  48 blocks, 512 threads.
// ---------------------------------------------------------------------------
__global__ __launch_bounds__(512) void spectrum_k2(
    const float* __restrict__ kk_arr,
    const float* __restrict__ Asp,
    const float* __restrict__ nsp,
    float* __restrict__ out)
{
    const int ell = blockIdx.x;
    const int tid = threadIdx.x;

    const float A_s  = Asp[0];
    const float n_s  = nsp[0];
    const float PI_F = 3.14159265358979323846f;
    const float pref = A_s * 2.0f * PI_F * PI_F;

    double tt = 0.0, ee = 0.0, te = 0.0;
    for (int i = tid; i < N_K; i += 512) {
        const float kv = kk_arr[i];
        const float wl = (i == 0)        ? 0.0f : (kv - kk_arr[i - 1]);
        const float wr = (i == N_K - 1)  ? 0.0f : (kk_arr[i + 1] - kv);
        const float pw = exp2f((n_s - 1.0f) * log2f(kv * 20.0f));
        const float weight = 0.5f * (wl + wr) * pref * pw / kv;

        float T = 0.f, E = 0.f;
        #pragma unroll
        for (int c = 0; c < N_CHUNK; ++c) {
            T += g_Tl[c][ell][i];
            E += g_El[c][ell][i];
        }
        tt += (double)(weight * T * T);
        ee += (double)(weight * E * E);
        te += (double)(weight * T * E);
    }

    #pragma unroll
    for (int o = 16; o > 0; o >>= 1) {
        tt += __shfl_down_sync(0xffffffffu, tt, o);
        ee += __shfl_down_sync(0xffffffffu, ee, o);
        te += __shfl_down_sync(0xffffffffu, te, o);
    }
    __shared__ double sT[16], sE[16], sX[16];
    const int wid = tid >> 5, lid = tid & 31;
    if (lid == 0) { sT[wid] = tt; sE[wid] = ee; sX[wid] = te; }
    __syncthreads();
    if (tid < 16) {
        tt = sT[tid]; ee = sE[tid]; te = sX[tid];
        #pragma unroll
        for (int o = 8; o > 0; o >>= 1) {
            tt += __shfl_down_sync(0xffffu, tt, o, 16);
            ee += __shfl_down_sync(0xffffu, ee, o, 16);
            te += __shfl_down_sync(0xffffu, te, o, 16);
        }
        if (tid == 0) {
            const double c = 2.0 / 3.14159265358979323846;
            out[0 * N_ELL + ell] = (float)(c * tt);
            out[1 * N_ELL + ell] = (float)(c * ee);
            out[2 * N_ELL + ell] = (float)(c * te);
        }
    }
}

extern "C" void kernel_launch(void* const* d_in, const int* in_sizes, int n_in,
                              void* d_out, int out_size)
{
    const float* k    = (const float*)d_in[0];
    const float* tau  = (const float*)d_in[1];
    const float* tau0 = (const float*)d_in[2];
    const float* S0   = (const float*)d_in[3];
    const float* S1   = (const float*)d_in[4];
    const float* S2   = (const float*)d_in[5];
    const float* SE   = (const float*)d_in[6];
    const float* bx   = (const float*)d_in[7];
    const float* p0   = (const float*)d_in[8];
    const float* p1   = (const float*)d_in[9];
    const float* p2   = (const float*)d_in[10];
    const float* pe   = (const float*)d_in[11];
    const float* As   = (const float*)d_in[12];
    const float* ns   = (const float*)d_in[13];
    float* out = (float*)d_out;

    prep_kernel<<<TAB_BLK + SRC_BLK, 256>>>(p0, p1, p2, pe,
                                            k, tau, tau0, S0, S1, S2, SE, bx);

    dim3 grid1(N_K / K_PER_BLOCK, N_CHUNK);   // (64, 12)
    dim3 block1(NG, K_PER_BLOCK);             // (12, 16) = 192 threads
    spectrum_k1<<<grid1, block1>>>();

    spectrum_k2<<<N_ELL, 512>>>(k, As, ns, out);
}